// round 2
// baseline (speedup 1.0000x reference)
#include <cuda_runtime.h>
#include <cuda_bf16.h>

// Problem constants
#define BB     32
#define NN     1024
#define DD     128
#define C_OUT  16
#define PP     16      // P*P
#define HG     32      // sqrt(N)
#define OUTW   128     // HG * P

// out[b,c,i,j] = ( x[b,n]·W[p] + emb[c]·W[p] + bias[p] ) * mask[b,c]
//   with n = gh*32+gw, p = ph*4+pw, i = gh*4+ph, j = gw*4+pw
//
// Grid: B * (N/128) = 256 blocks, 128 threads, one token row per thread.
__global__ __launch_bounds__(128, 8)
void qbd_kernel(const float* __restrict__ x,
                const float* __restrict__ mask,
                const float* __restrict__ emb,
                const float* __restrict__ W,
                const float* __restrict__ bias,
                float* __restrict__ out)
{
    __shared__ __align__(16) float sW[PP][DD];        // 8 KB
    __shared__ __align__(16) float sCBM[C_OUT][PP];   // (emb[c]·W[p] + bias[p]) * mask[b,c]
    __shared__ float sMask[C_OUT];

    const int t   = threadIdx.x;
    const int blk = blockIdx.x;
    const int b   = blk >> 3;          // batch
    const int n0  = (blk & 7) << 7;    // first token row of this block

    // ---- stage W (16x128 f32) into smem, coalesced float4 ----
    {
        const float4* Wv  = (const float4*)W;
        float4*       sWv = (float4*)&sW[0][0];
        #pragma unroll
        for (int i = 0; i < 4; i++)
            sWv[t + 128 * i] = Wv[t + 128 * i];
    }
    if (t < C_OUT) sMask[t] = mask[b * C_OUT + t];
    __syncthreads();

    // ---- per-block channel table: (emb[c]·W[p] + bias[p]) * mask[b,c] ----
    for (int i = t; i < C_OUT * PP; i += 128) {
        const int c = i >> 4;
        const int p = i & 15;
        float s = __ldg(bias + p);
        const float* e = emb + c * DD;
        #pragma unroll 8
        for (int d = 0; d < DD; d++)
            s = fmaf(__ldg(e + d), sW[p][d], s);
        sCBM[c][p] = s * sMask[c];
    }

    // ---- main dot products: this thread's row against all 16 W rows ----
    const int n = n0 + t;
    const float4* xr = (const float4*)(x + ((size_t)(b * NN + n) * DD));
    float acc[PP];
    #pragma unroll
    for (int p = 0; p < PP; p++) acc[p] = 0.f;

    #pragma unroll 8
    for (int d4 = 0; d4 < DD / 4; d4++) {
        const float4 xv = xr[d4];
        #pragma unroll
        for (int p = 0; p < PP; p++) {
            const float4 wv = *(const float4*)&sW[p][d4 * 4];   // broadcast
            acc[p] = fmaf(xv.x, wv.x,
                     fmaf(xv.y, wv.y,
                     fmaf(xv.z, wv.z,
                     fmaf(xv.w, wv.w, acc[p]))));
        }
    }

    __syncthreads();   // sCBM fully written before any thread reads it

    // ---- epilogue: 16 channels x 4 patch-rows, float4 stores (coalesced) ----
    const int gh = n >> 5;
    const int gw = n & 31;
    #pragma unroll
    for (int c = 0; c < C_OUT; c++) {
        const float mk = sMask[c];
        float* oc = out + ((size_t)(b * C_OUT + c) * OUTW + gh * 4) * OUTW + gw * 4;
        #pragma unroll
        for (int ph = 0; ph < 4; ph++) {
            const float4 cbm = *(const float4*)&sCBM[c][ph * 4];  // broadcast
            float4 v;
            v.x = fmaf(acc[ph * 4 + 0], mk, cbm.x);
            v.y = fmaf(acc[ph * 4 + 1], mk, cbm.y);
            v.z = fmaf(acc[ph * 4 + 2], mk, cbm.z);
            v.w = fmaf(acc[ph * 4 + 3], mk, cbm.w);
            *(float4*)(oc + ph * OUTW) = v;
        }
    }
}

extern "C" void kernel_launch(void* const* d_in, const int* in_sizes, int n_in,
                              void* d_out, int out_size)
{
    const float* x    = (const float*)d_in[0];   // (32,1024,128)
    const float* mask = (const float*)d_in[1];   // (32,16)
    const float* emb  = (const float*)d_in[2];   // (256,128) — only first 16 rows used
    const float* W    = (const float*)d_in[3];   // (16,128)
    const float* bias = (const float*)d_in[4];   // (16,)
    float* out = (float*)d_out;                  // (32,16,128,128)

    qbd_kernel<<<BB * (NN / 128), 128>>>(x, mask, emb, W, bias, out);
}